// round 1
// baseline (speedup 1.0000x reference)
#include <cuda_runtime.h>

// ---------------- scratch (static device globals; no allocation) ----------------
__device__ float g_qkv [8LL * 768  * 1024];   // [B][768][HW]  q(0:256)*scale, k(256:512), v(512:768)
__device__ float g_col [8LL * 2304 * 1024];   // im2col for 3x3 conv
__device__ float g_attn[8LL * 256  * 1024];   // attention output before final 1x1

// ---------------- im2col for 3x3 pad-1 conv on 32x32 ----------------
__global__ void im2col_kernel(const float* __restrict__ x, float* __restrict__ col) {
    long long idx = (long long)blockIdx.x * blockDim.x + threadIdx.x;   // exactly 8*2304*1024
    int p    = (int)(idx & 1023);
    long long t2 = idx >> 10;
    int kidx = (int)(t2 % 2304);
    int b    = (int)(t2 / 2304);
    int ci = kidx / 9, r = kidx % 9;
    int kh = r / 3, kw = r % 3;
    int y = p >> 5, xx = p & 31;
    int iy = y + kh - 1, ix = xx + kw - 1;
    float v = 0.f;
    if (iy >= 0 && iy < 32 && ix >= 0 && ix < 32)
        v = x[((long long)b * 256 + ci) * 1024 + iy * 32 + ix];
    col[idx] = v;
}

// ---------------- generic tiled SGEMM: C[b] = A @ X[b] + bias ----------------
// A: [M,K] row-major. X: per-batch [K,N]. C: per-batch rows offset by crow_off.
// Rows < qscale_rows of the result are multiplied by qscale (after bias).
// Requires: M%64==0, N%64==0, K%16==0 (true for all uses here).
__global__ void sgemm_bias(const float* __restrict__ A, const float* __restrict__ X,
                           float* __restrict__ C, const float* __restrict__ bias,
                           int M, int N, int K,
                           long long strideX, long long strideC, int crow_off,
                           float qscale, int qscale_rows)
{
    __shared__ float As[16][68];
    __shared__ float Xs[16][68];
    const int b = blockIdx.z;
    const float* Xb = X + (long long)b * strideX;
    float* Cb = C + (long long)b * strideC;
    const int row0 = blockIdx.y * 64, col0 = blockIdx.x * 64;
    const int t = threadIdx.x;
    const int ty = t >> 4, tx = t & 15;
    const int am = t >> 2, ak = (t & 3) * 4;     // A tile load: 64 rows x 16 k
    const int xk = t >> 4, xn = (t & 15) * 4;    // X tile load: 16 k x 64 n

    float acc[4][4];
#pragma unroll
    for (int i = 0; i < 4; i++)
#pragma unroll
        for (int j = 0; j < 4; j++) acc[i][j] = 0.f;

    for (int k0 = 0; k0 < K; k0 += 16) {
        float4 a4 = *(const float4*)&A[(long long)(row0 + am) * K + k0 + ak];
        As[ak + 0][am] = a4.x; As[ak + 1][am] = a4.y;
        As[ak + 2][am] = a4.z; As[ak + 3][am] = a4.w;
        *(float4*)&Xs[xk][xn] = *(const float4*)&Xb[(long long)(k0 + xk) * N + col0 + xn];
        __syncthreads();
#pragma unroll
        for (int kk = 0; kk < 16; kk++) {
            float4 av = *(const float4*)&As[kk][ty * 4];
            float4 xv = *(const float4*)&Xs[kk][tx * 4];
            float a[4] = {av.x, av.y, av.z, av.w};
            float xr[4] = {xv.x, xv.y, xv.z, xv.w};
#pragma unroll
            for (int i = 0; i < 4; i++)
#pragma unroll
                for (int j = 0; j < 4; j++) acc[i][j] = fmaf(a[i], xr[j], acc[i][j]);
        }
        __syncthreads();
    }
#pragma unroll
    for (int i = 0; i < 4; i++) {
        int r = row0 + ty * 4 + i;
        float bs = bias ? bias[r] : 0.f;
        float s = (r < qscale_rows) ? qscale : 1.f;
        float4 o;
        o.x = (acc[i][0] + bs) * s; o.y = (acc[i][1] + bs) * s;
        o.z = (acc[i][2] + bs) * s; o.w = (acc[i][3] + bs) * s;
        *(float4*)&Cb[(long long)(crow_off + r) * N + col0 + tx * 4] = o;
    }
}

// ---------------- fused attention: S = QK^T + rel, softmax, O = P V ----------------
// One block per (b, h, 32-query-row tile). Scores tile (32 x 1024) lives in smem.
// Queries in a tile share x = blockIdx.x; y = qi. rel terms:
//   S[qi][k] += Ew[qi][ yk - qi + 31 ] + Eh[qi][ xk - xq + 31 ]
#define SSTR 1028
__global__ void attn_kernel(const float* __restrict__ qkv,
                            const float* __restrict__ relw,  // [63][32]
                            const float* __restrict__ relh,  // [63][32]
                            float* __restrict__ attn_out)    // [B][256][1024]
{
    extern __shared__ float sm[];
    float* scores  = sm;                    // 32*1028
    float* q_sh    = scores  + 32 * SSTR;   // 32*36   [qi][d]
    float* kv_sh   = q_sh    + 32 * 36;     // 2304    (K^T tile / V tile / O stage)
    float* relw_sh = kv_sh   + 2304;        // 2016
    float* relh_sh = relw_sh + 2016;        // 2016
    float* ew      = relh_sh + 2016;        // 32*64
    float* eh      = ew      + 2048;        // 32*64
    float* sinv    = eh      + 2048;        // 32

    const int bh = blockIdx.y;
    const int b = bh >> 3, h = bh & 7;
    const int q0 = blockIdx.x * 32;
    const int xq = blockIdx.x;              // x coord of every query in this tile
    const int t = threadIdx.x;
    const int w = t >> 5, l = t & 31;

    const float* qb = qkv + ((long long)b * 768 +       h * 32) * 1024;
    const float* kb = qkv + ((long long)b * 768 + 256 + h * 32) * 1024;
    const float* vb = qkv + ((long long)b * 768 + 512 + h * 32) * 1024;

    for (int i = t; i < 2016; i += 256) { relw_sh[i] = relw[i]; relh_sh[i] = relh[i]; }
    for (int i = t; i < 1024; i += 256) {
        int d = i >> 5, qi = i & 31;
        q_sh[qi * 36 + d] = qb[d * 1024 + q0 + qi];
    }
    __syncthreads();

    // relative-position row tables Ew, Eh: [32 q][63 m]
    for (int e = t; e < 2016; e += 256) {
        int qi = e / 63, m = e % 63;
        float s1 = 0.f, s2 = 0.f;
#pragma unroll
        for (int d = 0; d < 32; d++) {
            float qv = q_sh[qi * 36 + d];
            s1 = fmaf(qv, relw_sh[m * 32 + d], s1);
            s2 = fmaf(qv, relh_sh[m * 32 + d], s2);
        }
        ew[qi * 64 + m] = s1; eh[qi * 64 + m] = s2;
    }
    __syncthreads();

    // ---- S = Q K^T (+rel), written into scores ----
    for (int k0 = 0; k0 < 1024; k0 += 64) {
        for (int i = t; i < 2048; i += 256) {          // K^T tile [kc][d], stride 36
            int d = i >> 6, kc = i & 63;
            kv_sh[kc * 36 + d] = kb[d * 1024 + k0 + kc];
        }
        __syncthreads();
        float acc[4][2];
#pragma unroll
        for (int j = 0; j < 4; j++) { acc[j][0] = 0.f; acc[j][1] = 0.f; }
#pragma unroll
        for (int d = 0; d < 32; d += 4) {
            float4 kv0 = *(const float4*)(kv_sh + l * 36 + d);
            float4 kv1 = *(const float4*)(kv_sh + (l + 32) * 36 + d);
#pragma unroll
            for (int j = 0; j < 4; j++) {
                float4 qv = *(const float4*)(q_sh + (w * 4 + j) * 36 + d);
                acc[j][0] += qv.x * kv0.x + qv.y * kv0.y + qv.z * kv0.z + qv.w * kv0.w;
                acc[j][1] += qv.x * kv1.x + qv.y * kv1.y + qv.z * kv1.z + qv.w * kv1.w;
            }
        }
        int xk = (k0 >> 5);                            // key x coord base (kk>>5 = xk + i)
#pragma unroll
        for (int i = 0; i < 2; i++) {
            int kk = k0 + l + 32 * i;
            int mh = xk + i - xq + 31;
#pragma unroll
            for (int j = 0; j < 4; j++) {
                int qi = w * 4 + j;
                scores[qi * SSTR + kk] = acc[j][i]
                    + ew[qi * 64 + (l - qi + 31)]      // yk = l since k0,32i are %32==0
                    + eh[qi * 64 + mh];
            }
        }
        __syncthreads();
    }

    // ---- softmax per row (leave rows un-normalized; 1/sum in sinv) ----
#pragma unroll
    for (int r = 0; r < 4; r++) {
        int qi = w * 4 + r;
        float* row = scores + qi * SSTR;
        float mx = -1e30f;
        for (int j = l; j < 1024; j += 32) mx = fmaxf(mx, row[j]);
#pragma unroll
        for (int o = 16; o; o >>= 1) mx = fmaxf(mx, __shfl_xor_sync(0xffffffffu, mx, o));
        float sum = 0.f;
        for (int j = l; j < 1024; j += 32) {
            float e = __expf(row[j] - mx);
            row[j] = e; sum += e;
        }
#pragma unroll
        for (int o = 16; o; o >>= 1) sum += __shfl_xor_sync(0xffffffffu, sum, o);
        if (l == 0) sinv[qi] = 1.f / sum;
    }
    __syncthreads();

    // ---- O = P V  (accumulate un-normalized, scale at the end) ----
    const int ty = t >> 4, tx = t & 15;
    float accO[2][2] = {{0.f, 0.f}, {0.f, 0.f}};
    for (int k0 = 0; k0 < 1024; k0 += 64) {
        for (int i = t * 4; i < 2048; i += 1024) {     // V tile [dv][kk], stride 68
            int dv = i >> 6, kk = i & 63;
            *(float4*)(kv_sh + dv * 68 + kk) = *(const float4*)(vb + dv * 1024 + k0 + kk);
        }
        __syncthreads();
#pragma unroll
        for (int kk = 0; kk < 64; kk += 4) {
            float4 p0 = *(const float4*)(scores + (ty * 2 + 0) * SSTR + k0 + kk);
            float4 p1 = *(const float4*)(scores + (ty * 2 + 1) * SSTR + k0 + kk);
            float4 v0 = *(const float4*)(kv_sh + tx * 68 + kk);
            float4 v1 = *(const float4*)(kv_sh + (tx + 16) * 68 + kk);
            accO[0][0] += p0.x * v0.x + p0.y * v0.y + p0.z * v0.z + p0.w * v0.w;
            accO[0][1] += p0.x * v1.x + p0.y * v1.y + p0.z * v1.z + p0.w * v1.w;
            accO[1][0] += p1.x * v0.x + p1.y * v0.y + p1.z * v0.z + p1.w * v0.w;
            accO[1][1] += p1.x * v1.x + p1.y * v1.y + p1.z * v1.z + p1.w * v1.w;
        }
        __syncthreads();
    }

    // stage O through shared for coalesced global writes
#pragma unroll
    for (int jj = 0; jj < 2; jj++)
#pragma unroll
        for (int ii = 0; ii < 2; ii++)
            kv_sh[(tx + 16 * ii) * 33 + ty * 2 + jj] = accO[jj][ii];
    __syncthreads();
    for (int i = t; i < 1024; i += 256) {
        int dv = i >> 5, qi = i & 31;
        attn_out[((long long)b * 256 + h * 32 + dv) * 1024 + q0 + qi] =
            kv_sh[dv * 33 + qi] * sinv[qi];
    }
}

// ---------------- launch ----------------
extern "C" void kernel_launch(void* const* d_in, const int* in_sizes, int n_in,
                              void* d_out, int out_size) {
    const float* x      = (const float*)d_in[0];
    const float* w_qkv  = (const float*)d_in[1];
    const float* b_qkv  = (const float*)d_in[2];
    const float* w_attn = (const float*)d_in[3];
    const float* b_attn = (const float*)d_in[4];
    const float* w_out  = (const float*)d_in[5];
    const float* b_out  = (const float*)d_in[6];
    const float* relw   = (const float*)d_in[7];
    const float* relh   = (const float*)d_in[8];
    float* out = (float*)d_out;

    float *qkv, *col, *attn;
    cudaGetSymbolAddress((void**)&qkv,  g_qkv);
    cudaGetSymbolAddress((void**)&col,  g_col);
    cudaGetSymbolAddress((void**)&attn, g_attn);

    const int SMEM_BYTES = (32 * SSTR + 32 * 36 + 2304 + 2016 + 2016 + 2048 + 2048 + 32) * 4;
    cudaFuncSetAttribute(attn_kernel, cudaFuncAttributeMaxDynamicSharedMemorySize, SMEM_BYTES);

    // conv path: im2col + GEMM -> out channels [0,256)
    im2col_kernel<<<73728, 256>>>(x, col);

    // qkv 1x1: [768,256]x[256,1024], scale q rows by dkh^-0.5
    sgemm_bias<<<dim3(16, 12, 8), 256>>>(w_qkv, x, qkv, b_qkv,
                                         768, 1024, 256,
                                         256LL * 1024, 768LL * 1024, 0,
                                         0.17677669529663687f, 256);

    // conv GEMM: [256,2304]x[2304,1024] -> out rows 0..255
    sgemm_bias<<<dim3(16, 4, 8), 256>>>(w_out, col, out, b_out,
                                        256, 1024, 2304,
                                        2304LL * 1024, 512LL * 1024, 0,
                                        1.f, 0);

    // fused attention
    attn_kernel<<<dim3(32, 64), 256, SMEM_BYTES>>>(qkv, relw, relh, attn);

    // final 1x1: [256,256]x[256,1024] -> out rows 256..511
    sgemm_bias<<<dim3(16, 4, 8), 256>>>(w_attn, attn, out, b_attn,
                                        256, 1024, 256,
                                        256LL * 1024, 512LL * 1024, 256,
                                        1.f, 0);
}

// round 2
// speedup vs baseline: 1.7412x; 1.7412x over previous
#include <cuda_runtime.h>

// ---------------- scratch ----------------
__device__ float g_qkv [8LL * 768  * 1024];
__device__ float g_col [8LL * 2304 * 1024];
__device__ float g_attn[8LL * 256  * 1024];

// ---------------- im2col ----------------
__global__ void im2col_kernel(const float* __restrict__ x, float* __restrict__ col) {
    long long idx = (long long)blockIdx.x * blockDim.x + threadIdx.x;
    int p    = (int)(idx & 1023);
    long long t2 = idx >> 10;
    int kidx = (int)(t2 % 2304);
    int b    = (int)(t2 / 2304);
    int ci = kidx / 9, r = kidx % 9;
    int kh = r / 3, kw = r % 3;
    int y = p >> 5, xx = p & 31;
    int iy = y + kh - 1, ix = xx + kw - 1;
    float v = 0.f;
    if (iy >= 0 && iy < 32 && ix >= 0 && ix < 32)
        v = x[((long long)b * 256 + ci) * 1024 + iy * 32 + ix];
    col[idx] = v;
}

// ---------------- SGEMM 128x128, BK=16, 8x8 per thread, prefetch ----------------
// A:[M,K] row-major, X: per-batch [K,N]. Requires M%128==0, N%128==0, K%16==0.
__global__ __launch_bounds__(256) void sgemm128(
    const float* __restrict__ A, const float* __restrict__ X,
    float* __restrict__ C, const float* __restrict__ bias,
    int M, int N, int K, long long sX, long long sC, int crow,
    float qscale, int qrows)
{
    __shared__ float As[16][132];
    __shared__ float Bs[16][128];
    const int b = blockIdx.z;
    const float* Xb = X + (long long)b * sX;
    float* Cb = C + (long long)b * sC;
    const int row0 = blockIdx.y * 128, col0 = blockIdx.x * 128;
    const int t = threadIdx.x;
    const int tx = t & 15, ty = t >> 4;
    const int ar = t >> 1, ak = (t & 1) * 8;
    const int bk = t >> 4, bn = (t & 15) * 8;

    const float* Aptr = A + (long long)(row0 + ar) * K + ak;
    const float* Xptr = Xb + (long long)bk * N + col0 + bn;

    float4 pa0 = *(const float4*)(Aptr + 0);
    float4 pa1 = *(const float4*)(Aptr + 4);
    float4 pb0 = *(const float4*)(Xptr + 0);
    float4 pb1 = *(const float4*)(Xptr + 4);

    float acc[8][8];
#pragma unroll
    for (int i = 0; i < 8; i++)
#pragma unroll
        for (int j = 0; j < 8; j++) acc[i][j] = 0.f;

    for (int k0 = 0;; ) {
        As[ak + 0][ar] = pa0.x; As[ak + 1][ar] = pa0.y;
        As[ak + 2][ar] = pa0.z; As[ak + 3][ar] = pa0.w;
        As[ak + 4][ar] = pa1.x; As[ak + 5][ar] = pa1.y;
        As[ak + 6][ar] = pa1.z; As[ak + 7][ar] = pa1.w;
        *(float4*)&Bs[bk][bn]     = pb0;
        *(float4*)&Bs[bk][bn + 4] = pb1;
        __syncthreads();

        bool last = (k0 + 16 >= K);
        if (!last) {
            pa0 = *(const float4*)(Aptr + k0 + 16);
            pa1 = *(const float4*)(Aptr + k0 + 20);
            pb0 = *(const float4*)(Xptr + (long long)(k0 + 16) * N);
            pb1 = *(const float4*)(Xptr + (long long)(k0 + 16) * N + 4);
        }
#pragma unroll
        for (int kk = 0; kk < 16; kk++) {
            float4 a0 = *(const float4*)&As[kk][ty * 8];
            float4 a1 = *(const float4*)&As[kk][ty * 8 + 4];
            float4 b0 = *(const float4*)&Bs[kk][tx * 8];
            float4 b1 = *(const float4*)&Bs[kk][tx * 8 + 4];
            float av[8] = {a0.x, a0.y, a0.z, a0.w, a1.x, a1.y, a1.z, a1.w};
            float bv[8] = {b0.x, b0.y, b0.z, b0.w, b1.x, b1.y, b1.z, b1.w};
#pragma unroll
            for (int i = 0; i < 8; i++)
#pragma unroll
                for (int j = 0; j < 8; j++)
                    acc[i][j] = fmaf(av[i], bv[j], acc[i][j]);
        }
        __syncthreads();
        k0 += 16;
        if (last) break;
    }

#pragma unroll
    for (int i = 0; i < 8; i++) {
        int r = row0 + ty * 8 + i;
        float bs = bias ? bias[r] : 0.f;
        float s = (r < qrows) ? qscale : 1.f;
        float4 o0, o1;
        o0.x = (acc[i][0] + bs) * s; o0.y = (acc[i][1] + bs) * s;
        o0.z = (acc[i][2] + bs) * s; o0.w = (acc[i][3] + bs) * s;
        o1.x = (acc[i][4] + bs) * s; o1.y = (acc[i][5] + bs) * s;
        o1.z = (acc[i][6] + bs) * s; o1.w = (acc[i][7] + bs) * s;
        *(float4*)&Cb[(long long)(crow + r) * N + col0 + tx * 8]     = o0;
        *(float4*)&Cb[(long long)(crow + r) * N + col0 + tx * 8 + 4] = o1;
    }
}

// ---------------- flash attention, 64 queries/block ----------------
// query pos p = q0+qi: w-coord = qi&31, h-coord = 2*bx + (qi>>5)
// S[qi][k] += ew[qi][(k&31)-(qi&31)+31] + eh[qi][(k>>5)-hq+31]
__global__ __launch_bounds__(256) void attn_kernel(
    const float* __restrict__ qkv,
    const float* __restrict__ relw,   // [63][32]
    const float* __restrict__ relh,   // [63][32]
    float* __restrict__ attn_out)     // [B][256][1024]
{
    extern __shared__ float sm[];
    float* q_t    = sm;               // [32 d][68]
    float* k_t    = q_t    + 32 * 68; // [32 d][68]
    float* v_nt   = k_t    + 32 * 68; // [32 dv][68]  (k contiguous)
    float* p_q    = v_nt   + 32 * 68; // [64 q][68]   (k contiguous; reused as out stage)
    float* relcat = p_q    + 64 * 68; // [32 d][132]  cols 0..62 relw, 64..126 relh
    float* ew     = relcat + 32 * 132;// [64 q][64]
    float* eh     = ew     + 64 * 64; // [64 q][64]

    const int bh = blockIdx.y;
    const int b = bh >> 3, h = bh & 7;
    const int bx = blockIdx.x;
    const int q0 = bx * 64;
    const int t = threadIdx.x;
    const int tx = t & 15, ty = t >> 4;

    const float* qb = qkv + ((long long)b * 768 +       h * 32) * 1024;
    const float* kb = qkv + ((long long)b * 768 + 256 + h * 32) * 1024;
    const float* vb = qkv + ((long long)b * 768 + 512 + h * 32) * 1024;

    for (int i = t; i < 2048; i += 256) {
        int d = i >> 6, qi = i & 63;
        q_t[d * 68 + qi] = qb[d * 1024 + q0 + qi];
    }
    for (int i = t; i < 4096; i += 256) {
        int d = i >> 7, c = i & 127;
        int m = c & 63;
        float v = 0.f;
        if (m < 63) v = (c < 64) ? relw[m * 32 + d] : relh[m * 32 + d];
        relcat[d * 132 + c] = v;
    }
    __syncthreads();

    // ew/eh as a 64x128 GEMM over d=32 (two 64-col passes)
#pragma unroll
    for (int pass = 0; pass < 2; pass++) {
        float a[4][4];
#pragma unroll
        for (int j = 0; j < 4; j++)
#pragma unroll
            for (int i = 0; i < 4; i++) a[j][i] = 0.f;
#pragma unroll
        for (int d = 0; d < 32; d++) {
            float4 qv = *(const float4*)(q_t + d * 68 + ty * 4);
            float4 rv = *(const float4*)(relcat + d * 132 + pass * 64 + tx * 4);
            float q4[4] = {qv.x, qv.y, qv.z, qv.w};
            float r4[4] = {rv.x, rv.y, rv.z, rv.w};
#pragma unroll
            for (int j = 0; j < 4; j++)
#pragma unroll
                for (int i = 0; i < 4; i++) a[j][i] = fmaf(q4[j], r4[i], a[j][i]);
        }
        float* dst = pass ? eh : ew;
#pragma unroll
        for (int j = 0; j < 4; j++)
#pragma unroll
            for (int i = 0; i < 4; i++)
                dst[(ty * 4 + j) * 64 + tx * 4 + i] = a[j][i];
    }
    __syncthreads();

    // hoisted rel terms
    const int hq = bx * 2 + (ty >> 3);        // h-coord of this thread's q rows
    float ewv[4][4];
#pragma unroll
    for (int j = 0; j < 4; j++) {
        int qi = ty * 4 + j;
#pragma unroll
        for (int i = 0; i < 4; i++)
            ewv[j][i] = ew[qi * 64 + ((tx * 4 + i) & 31) - (qi & 31) + 31];
    }
    const int khalf = tx >> 3;                // (tx*4+i)>>5 for all i

    float m_j[4] = {-1e30f, -1e30f, -1e30f, -1e30f};
    float s_j[4] = {0.f, 0.f, 0.f, 0.f};
    float ov[4][2];
#pragma unroll
    for (int j = 0; j < 4; j++) { ov[j][0] = 0.f; ov[j][1] = 0.f; }

    for (int k0 = 0; k0 < 1024; k0 += 64) {
        __syncthreads();   // protect k_t/v_nt/p_q from previous iteration's readers
        for (int i = t; i < 2048; i += 256) {
            int d = i >> 6, kc = i & 63;
            k_t [d * 68 + kc] = kb[d * 1024 + k0 + kc];
            v_nt[d * 68 + kc] = vb[d * 1024 + k0 + kc];
        }
        __syncthreads();

        float acc[4][4];
#pragma unroll
        for (int j = 0; j < 4; j++)
#pragma unroll
            for (int i = 0; i < 4; i++) acc[j][i] = 0.f;
#pragma unroll
        for (int d = 0; d < 32; d++) {
            float4 qv = *(const float4*)(q_t + d * 68 + ty * 4);
            float4 kv = *(const float4*)(k_t + d * 68 + tx * 4);
            float q4[4] = {qv.x, qv.y, qv.z, qv.w};
            float k4[4] = {kv.x, kv.y, kv.z, kv.w};
#pragma unroll
            for (int j = 0; j < 4; j++)
#pragma unroll
                for (int i = 0; i < 4; i++) acc[j][i] = fmaf(q4[j], k4[i], acc[j][i]);
        }

        const int mh = (k0 >> 5) + khalf - hq + 31;
#pragma unroll
        for (int j = 0; j < 4; j++) {
            float ehv = eh[(ty * 4 + j) * 64 + mh];
            float mx = -1e30f;
#pragma unroll
            for (int i = 0; i < 4; i++) {
                acc[j][i] += ewv[j][i] + ehv;
                mx = fmaxf(mx, acc[j][i]);
            }
#pragma unroll
            for (int o = 1; o < 16; o <<= 1)
                mx = fmaxf(mx, __shfl_xor_sync(0xffffffffu, mx, o));
            float nm = fmaxf(m_j[j], mx);
            float sc = __expf(m_j[j] - nm);
            float rs = 0.f;
#pragma unroll
            for (int i = 0; i < 4; i++) {
                float p = __expf(acc[j][i] - nm);
                acc[j][i] = p; rs += p;
            }
#pragma unroll
            for (int o = 1; o < 16; o <<= 1)
                rs += __shfl_xor_sync(0xffffffffu, rs, o);
            s_j[j] = s_j[j] * sc + rs;
            m_j[j] = nm;
            ov[j][0] *= sc; ov[j][1] *= sc;
            *(float4*)(p_q + (ty * 4 + j) * 68 + tx * 4) =
                make_float4(acc[j][0], acc[j][1], acc[j][2], acc[j][3]);
        }
        __syncthreads();

        // O[q][dv] += sum_k P[q][k] * V[dv][k]
#pragma unroll
        for (int kk = 0; kk < 64; kk += 4) {
            float4 va = *(const float4*)(v_nt + (tx * 2 + 0) * 68 + kk);
            float4 vb4 = *(const float4*)(v_nt + (tx * 2 + 1) * 68 + kk);
#pragma unroll
            for (int j = 0; j < 4; j++) {
                float4 p = *(const float4*)(p_q + (ty * 4 + j) * 68 + kk);
                ov[j][0] += p.x * va.x + p.y * va.y + p.z * va.z + p.w * va.w;
                ov[j][1] += p.x * vb4.x + p.y * vb4.y + p.z * vb4.z + p.w * vb4.w;
            }
        }
    }

    __syncthreads();
#pragma unroll
    for (int j = 0; j < 4; j++) {
        float inv = 1.f / s_j[j];
        p_q[(tx * 2 + 0) * 68 + ty * 4 + j] = ov[j][0] * inv;
        p_q[(tx * 2 + 1) * 68 + ty * 4 + j] = ov[j][1] * inv;
    }
    __syncthreads();
    for (int i = t; i < 2048; i += 256) {
        int dv = i >> 6, qi = i & 63;
        attn_out[((long long)b * 256 + h * 32 + dv) * 1024 + q0 + qi] = p_q[dv * 68 + qi];
    }
}

// ---------------- launch ----------------
extern "C" void kernel_launch(void* const* d_in, const int* in_sizes, int n_in,
                              void* d_out, int out_size) {
    const float* x      = (const float*)d_in[0];
    const float* w_qkv  = (const float*)d_in[1];
    const float* b_qkv  = (const float*)d_in[2];
    const float* w_attn = (const float*)d_in[3];
    const float* b_attn = (const float*)d_in[4];
    const float* w_out  = (const float*)d_in[5];
    const float* b_out  = (const float*)d_in[6];
    const float* relw   = (const float*)d_in[7];
    const float* relh   = (const float*)d_in[8];
    float* out = (float*)d_out;

    float *qkv, *col, *attn;
    cudaGetSymbolAddress((void**)&qkv,  g_qkv);
    cudaGetSymbolAddress((void**)&col,  g_col);
    cudaGetSymbolAddress((void**)&attn, g_attn);

    const int ATTN_SMEM = (32*68*3 + 64*68 + 32*132 + 64*64*2) * 4;
    cudaFuncSetAttribute(attn_kernel, cudaFuncAttributeMaxDynamicSharedMemorySize, ATTN_SMEM);

    im2col_kernel<<<73728, 256>>>(x, col);

    // qkv 1x1: [768,256]x[256,1024], q rows scaled by dkh^-0.5
    sgemm128<<<dim3(8, 6, 8), 256>>>(w_qkv, x, qkv, b_qkv,
                                     768, 1024, 256,
                                     256LL * 1024, 768LL * 1024, 0,
                                     0.17677669529663687f, 256);

    // conv GEMM: [256,2304]x[2304,1024] -> out rows 0..255
    sgemm128<<<dim3(8, 2, 8), 256>>>(w_out, col, out, b_out,
                                     256, 1024, 2304,
                                     2304LL * 1024, 512LL * 1024, 0,
                                     1.f, 0);

    attn_kernel<<<dim3(16, 64), 256, ATTN_SMEM>>>(qkv, relw, relh, attn);

    // final 1x1: [256,256]x[256,1024] -> out rows 256..511
    sgemm128<<<dim3(8, 2, 8), 256>>>(w_attn, attn, out, b_attn,
                                     256, 1024, 256,
                                     256LL * 1024, 512LL * 1024, 256,
                                     1.f, 0);
}

// round 3
// speedup vs baseline: 3.3421x; 1.9194x over previous
#include <cuda_runtime.h>

// ---------------- scratch ----------------
__device__ float g_qkv [8LL * 768  * 1024];
__device__ float g_col [8LL * 2304 * 1024];
__device__ float g_attn[8LL * 256  * 1024];

__device__ __forceinline__ unsigned cvt_tf32(float x) {
    unsigned r;
    asm("cvt.rna.tf32.f32 %0, %1;" : "=r"(r) : "f"(x));
    return r;
}
__device__ __forceinline__ void mma_tf32(float4& c, unsigned a0, unsigned a1,
                                         unsigned a2, unsigned a3,
                                         unsigned b0, unsigned b1) {
    asm volatile(
        "mma.sync.aligned.m16n8k8.row.col.f32.tf32.tf32.f32 "
        "{%0,%1,%2,%3}, {%4,%5,%6,%7}, {%8,%9}, {%0,%1,%2,%3};"
        : "+f"(c.x), "+f"(c.y), "+f"(c.z), "+f"(c.w)
        : "r"(a0), "r"(a1), "r"(a2), "r"(a3), "r"(b0), "r"(b1));
}

// ---------------- im2col ----------------
__global__ void im2col_kernel(const float* __restrict__ x, float* __restrict__ col) {
    long long idx = (long long)blockIdx.x * blockDim.x + threadIdx.x;
    int p    = (int)(idx & 1023);
    long long t2 = idx >> 10;
    int kidx = (int)(t2 % 2304);
    int b    = (int)(t2 / 2304);
    int ci = kidx / 9, r = kidx % 9;
    int kh = r / 3, kw = r % 3;
    int y = p >> 5, xx = p & 31;
    int iy = y + kh - 1, ix = xx + kw - 1;
    float v = 0.f;
    if (iy >= 0 && iy < 32 && ix >= 0 && ix < 32)
        v = x[((long long)b * 256 + ci) * 1024 + iy * 32 + ix];
    col[idx] = v;
}

// ---------------- tf32 tensor-core GEMM: 128x128 tile, BK=32, 8 warps ----------------
// A:[M,K] row-major, X: per-batch [K,N]. M%128==0, N%128==0, K%32==0.
__global__ __launch_bounds__(256) void sgemm_tf32(
    const float* __restrict__ A, const float* __restrict__ X,
    float* __restrict__ C, const float* __restrict__ bias,
    int M, int N, int K, long long sX, long long sC, int crow,
    float qscale, int qrows)
{
    __shared__ float As[32 * 136];   // [k][m]
    __shared__ float Bs[32 * 136];   // [k][n]
    const int bz = blockIdx.z;
    const float* Xb = X + (long long)bz * sX;
    float* Cb = C + (long long)bz * sC;
    const int row0 = blockIdx.y * 128, col0 = blockIdx.x * 128;
    const int t = threadIdx.x;
    const int wid = t >> 5, lane = t & 31;
    const int gid = lane >> 2, tig = lane & 3;
    const int wm = wid >> 1, wn = wid & 1;

    const int ar = t >> 1, aks = (t & 1) * 16;
    const int br = t >> 3, bc = (t & 7) * 4;
    const float* Ap = A + (long long)(row0 + ar) * K + aks;
    const float* Xp = Xb + (long long)br * N + col0 + bc;

    float4 pa[4], pb[4];
#pragma unroll
    for (int j = 0; j < 4; j++) {
        pa[j] = *(const float4*)(Ap + 4 * j);
        pb[j] = *(const float4*)(Xp + 32 * j);
    }

    float4 acc[2][8];
#pragma unroll
    for (int mt = 0; mt < 2; mt++)
#pragma unroll
        for (int nt = 0; nt < 8; nt++) acc[mt][nt] = make_float4(0.f, 0.f, 0.f, 0.f);

    for (int k0 = 0;; ) {
#pragma unroll
        for (int j = 0; j < 4; j++) {
            As[(aks + 4 * j + 0) * 136 + ar] = __uint_as_float(cvt_tf32(pa[j].x));
            As[(aks + 4 * j + 1) * 136 + ar] = __uint_as_float(cvt_tf32(pa[j].y));
            As[(aks + 4 * j + 2) * 136 + ar] = __uint_as_float(cvt_tf32(pa[j].z));
            As[(aks + 4 * j + 3) * 136 + ar] = __uint_as_float(cvt_tf32(pa[j].w));
            float4 bb;
            bb.x = __uint_as_float(cvt_tf32(pb[j].x));
            bb.y = __uint_as_float(cvt_tf32(pb[j].y));
            bb.z = __uint_as_float(cvt_tf32(pb[j].z));
            bb.w = __uint_as_float(cvt_tf32(pb[j].w));
            *(float4*)&Bs[br * 136 + bc + 32 * j] = bb;
        }
        __syncthreads();

        bool last = (k0 + 32 >= K);
        if (!last) {
#pragma unroll
            for (int j = 0; j < 4; j++) {
                pa[j] = *(const float4*)(Ap + k0 + 32 + 4 * j);
                pb[j] = *(const float4*)(Xp + (long long)(k0 + 32) * N + 32 * j);
            }
        }
#pragma unroll
        for (int ks = 0; ks < 4; ks++) {
            const int kk = ks * 8;
            unsigned a[2][4];
#pragma unroll
            for (int mt = 0; mt < 2; mt++) {
                int m0 = wm * 32 + mt * 16;
                a[mt][0] = __float_as_uint(As[(kk + tig) * 136 + m0 + gid]);
                a[mt][1] = __float_as_uint(As[(kk + tig) * 136 + m0 + gid + 8]);
                a[mt][2] = __float_as_uint(As[(kk + tig + 4) * 136 + m0 + gid]);
                a[mt][3] = __float_as_uint(As[(kk + tig + 4) * 136 + m0 + gid + 8]);
            }
#pragma unroll
            for (int nt = 0; nt < 8; nt++) {
                int n0 = wn * 64 + nt * 8;
                unsigned b0 = __float_as_uint(Bs[(kk + tig) * 136 + n0 + gid]);
                unsigned b1 = __float_as_uint(Bs[(kk + tig + 4) * 136 + n0 + gid]);
                mma_tf32(acc[0][nt], a[0][0], a[0][1], a[0][2], a[0][3], b0, b1);
                mma_tf32(acc[1][nt], a[1][0], a[1][1], a[1][2], a[1][3], b0, b1);
            }
        }
        __syncthreads();
        k0 += 32;
        if (last) break;
    }

#pragma unroll
    for (int mt = 0; mt < 2; mt++) {
        int rA = row0 + wm * 32 + mt * 16 + gid;
        int rB = rA + 8;
        float bA = bias ? bias[rA] : 0.f, bB = bias ? bias[rB] : 0.f;
        float sA = (rA < qrows) ? qscale : 1.f, sB = (rB < qrows) ? qscale : 1.f;
#pragma unroll
        for (int nt = 0; nt < 8; nt++) {
            int cc = col0 + wn * 64 + nt * 8 + 2 * tig;
            float2 oA = make_float2((acc[mt][nt].x + bA) * sA, (acc[mt][nt].y + bA) * sA);
            float2 oB = make_float2((acc[mt][nt].z + bB) * sB, (acc[mt][nt].w + bB) * sB);
            *(float2*)&Cb[(long long)(crow + rA) * N + cc] = oA;
            *(float2*)&Cb[(long long)(crow + rB) * N + cc] = oB;
        }
    }
}

// ---------------- tensor-core flash attention, 64 q / block, 4 warps ----------------
#define KSQ 0
#define VSO 2304
#define PSO 4608
#define EHO 9216
#define RLO 13312
#define SCO 17472
#define ATTN_SM_FLOATS 17536

__global__ __launch_bounds__(128) void attn_mma(
    const float* __restrict__ qkv,
    const float* __restrict__ relw,   // [63][32]
    const float* __restrict__ relh,   // [63][32]
    float* __restrict__ attn_out)     // [B][256][1024]
{
    extern __shared__ float sm[];
    const int bh = blockIdx.y;
    const int b = bh >> 3, h = bh & 7;
    const int bx = blockIdx.x;
    const int q0 = bx * 64;
    const int t = threadIdx.x;
    const int wid = t >> 5, lane = t & 31;
    const int gid = lane >> 2, tig = lane & 3;
    const int qrow = wid * 16;

    const float* qb = qkv + ((long long)b * 768 +       h * 32) * 1024;
    const float* kb = qkv + ((long long)b * 768 + 256 + h * 32) * 1024;
    const float* vb = qkv + ((long long)b * 768 + 512 + h * 32) * 1024;

    // Q (raw fp32) into Ks region [d][q] stride 72; stage rel tables stride 33
    for (int i = t; i < 2048; i += 128) {
        int d = i >> 6, qi = i & 63;
        sm[KSQ + d * 72 + qi] = qb[d * 1024 + q0 + qi];
    }
    for (int i = t; i < 2016; i += 128) {
        int m = i >> 5, d = i & 31;
        sm[RLO + m * 33 + d]        = relw[i];
        sm[RLO + 2079 + m * 33 + d] = relh[i];
    }
    __syncthreads();

    // ew table -> Ps region, eh table -> EHO (flat [qi*64+m])
    for (int e = t; e < 8192; e += 128) {
        int idx = e & 4095, qi = idx >> 6, m = idx & 63;
        float s = 0.f;
        if (m < 63) {
            const float* r = sm + RLO + (e >> 12) * 2079 + m * 33;
#pragma unroll
            for (int d = 0; d < 32; d++) s = fmaf(sm[KSQ + d * 72 + qi], r[d], s);
        }
        if (e < 4096) sm[PSO + idx] = s; else sm[EHO + idx] = s;
    }
    __syncthreads();

    // Q a-fragments (A row-major m16k8), kept in registers
    unsigned qa[4][4];
#pragma unroll
    for (int ks = 0; ks < 4; ks++) {
        int kd = ks * 8;
        qa[ks][0] = cvt_tf32(sm[KSQ + (kd + tig) * 72 + qrow + gid]);
        qa[ks][1] = cvt_tf32(sm[KSQ + (kd + tig) * 72 + qrow + gid + 8]);
        qa[ks][2] = cvt_tf32(sm[KSQ + (kd + tig + 4) * 72 + qrow + gid]);
        qa[ks][3] = cvt_tf32(sm[KSQ + (kd + tig + 4) * 72 + qrow + gid + 8]);
    }
    // hoisted ew terms (k-tile periodic): [row A/B][nt&3 * 2 + j]
    float ewreg[2][8];
    const int qiA = qrow + gid, qiB = qiA + 8;
#pragma unroll
    for (int nt = 0; nt < 4; nt++)
#pragma unroll
        for (int j = 0; j < 2; j++) {
            int yk = nt * 8 + tig * 2 + j;
            ewreg[0][nt * 2 + j] = sm[PSO + qiA * 64 + yk - (qiA & 31) + 31];
            ewreg[1][nt * 2 + j] = sm[PSO + qiB * 64 + yk - (qiB & 31) + 31];
        }
    const int hqA = 2 * bx + (qiA >> 5);
    const int hqB = 2 * bx + (qiB >> 5);

    float mA = -1e30f, mB = -1e30f, sA = 0.f, sB = 0.f;
    float4 oc[2][2];    // O^T c-frags: [mt: dv half][nt2: q octet]
#pragma unroll
    for (int mt = 0; mt < 2; mt++)
#pragma unroll
        for (int n2 = 0; n2 < 2; n2++) oc[mt][n2] = make_float4(0.f, 0.f, 0.f, 0.f);

    for (int k0 = 0; k0 < 1024; k0 += 64) {
        __syncthreads();
        for (int i = t; i < 2048; i += 128) {
            int d = i >> 6, c = i & 63;
            sm[KSQ + d * 72 + c] = __uint_as_float(cvt_tf32(kb[d * 1024 + k0 + c]));
            sm[VSO + d * 72 + c] = __uint_as_float(cvt_tf32(vb[d * 1024 + k0 + c]));
        }
        __syncthreads();

        // S = Q K^T
        float4 sc4[8];
#pragma unroll
        for (int nt = 0; nt < 8; nt++) sc4[nt] = make_float4(0.f, 0.f, 0.f, 0.f);
#pragma unroll
        for (int ks = 0; ks < 4; ks++) {
            int kd = ks * 8;
#pragma unroll
            for (int nt = 0; nt < 8; nt++) {
                unsigned b0 = __float_as_uint(sm[KSQ + (kd + tig) * 72 + nt * 8 + gid]);
                unsigned b1 = __float_as_uint(sm[KSQ + (kd + tig + 4) * 72 + nt * 8 + gid]);
                mma_tf32(sc4[nt], qa[ks][0], qa[ks][1], qa[ks][2], qa[ks][3], b0, b1);
            }
        }

        // rel logits + online softmax
        int xk = k0 >> 5;
        float ehA0 = sm[EHO + qiA * 64 + xk - hqA + 31];
        float ehA1 = sm[EHO + qiA * 64 + xk + 1 - hqA + 31];
        float ehB0 = sm[EHO + qiB * 64 + xk - hqB + 31];
        float ehB1 = sm[EHO + qiB * 64 + xk + 1 - hqB + 31];
        float mxA = -1e30f, mxB = -1e30f;
#pragma unroll
        for (int nt = 0; nt < 8; nt++) {
            float ha = (nt < 4) ? ehA0 : ehA1;
            float hb = (nt < 4) ? ehB0 : ehB1;
            sc4[nt].x += ewreg[0][(nt & 3) * 2 + 0] + ha;
            sc4[nt].y += ewreg[0][(nt & 3) * 2 + 1] + ha;
            sc4[nt].z += ewreg[1][(nt & 3) * 2 + 0] + hb;
            sc4[nt].w += ewreg[1][(nt & 3) * 2 + 1] + hb;
            mxA = fmaxf(mxA, fmaxf(sc4[nt].x, sc4[nt].y));
            mxB = fmaxf(mxB, fmaxf(sc4[nt].z, sc4[nt].w));
        }
        mxA = fmaxf(mxA, __shfl_xor_sync(0xffffffffu, mxA, 1));
        mxA = fmaxf(mxA, __shfl_xor_sync(0xffffffffu, mxA, 2));
        mxB = fmaxf(mxB, __shfl_xor_sync(0xffffffffu, mxB, 1));
        mxB = fmaxf(mxB, __shfl_xor_sync(0xffffffffu, mxB, 2));
        float nmA = fmaxf(mA, mxA), nmB = fmaxf(mB, mxB);
        float scA = __expf(mA - nmA), scB = __expf(mB - nmB);
        float rsA = 0.f, rsB = 0.f;
#pragma unroll
        for (int nt = 0; nt < 8; nt++) {
            float px = __expf(sc4[nt].x - nmA), py = __expf(sc4[nt].y - nmA);
            float pz = __expf(sc4[nt].z - nmB), pw = __expf(sc4[nt].w - nmB);
            rsA += px + py; rsB += pz + pw;
            int cc = nt * 8 + 2 * tig;
            *(float2*)&sm[PSO + qiA * 72 + cc] =
                make_float2(__uint_as_float(cvt_tf32(px)), __uint_as_float(cvt_tf32(py)));
            *(float2*)&sm[PSO + qiB * 72 + cc] =
                make_float2(__uint_as_float(cvt_tf32(pz)), __uint_as_float(cvt_tf32(pw)));
        }
        rsA += __shfl_xor_sync(0xffffffffu, rsA, 1);
        rsA += __shfl_xor_sync(0xffffffffu, rsA, 2);
        rsB += __shfl_xor_sync(0xffffffffu, rsB, 1);
        rsB += __shfl_xor_sync(0xffffffffu, rsB, 2);
        sA = sA * scA + rsA; mA = nmA;
        sB = sB * scB + rsB; mB = nmB;
        if (tig == 0) { sm[SCO + qiA] = scA; sm[SCO + qiB] = scB; }
        __syncthreads();

        // O^T = V P^T  (rescale O first)
        float scq[2][2];
#pragma unroll
        for (int n2 = 0; n2 < 2; n2++)
#pragma unroll
            for (int j = 0; j < 2; j++)
                scq[n2][j] = sm[SCO + qrow + n2 * 8 + 2 * tig + j];
#pragma unroll
        for (int mt = 0; mt < 2; mt++)
#pragma unroll
            for (int n2 = 0; n2 < 2; n2++) {
                oc[mt][n2].x *= scq[n2][0]; oc[mt][n2].y *= scq[n2][1];
                oc[mt][n2].z *= scq[n2][0]; oc[mt][n2].w *= scq[n2][1];
            }
#pragma unroll
        for (int ks = 0; ks < 8; ks++) {
            int kk = ks * 8;
            unsigned p0[2], p1[2];
#pragma unroll
            for (int n2 = 0; n2 < 2; n2++) {
                p0[n2] = __float_as_uint(sm[PSO + (qrow + n2 * 8 + gid) * 72 + kk + tig]);
                p1[n2] = __float_as_uint(sm[PSO + (qrow + n2 * 8 + gid) * 72 + kk + tig + 4]);
            }
#pragma unroll
            for (int mt = 0; mt < 2; mt++) {
                int dv0 = mt * 16;
                unsigned a0 = __float_as_uint(sm[VSO + (dv0 + gid) * 72 + kk + tig]);
                unsigned a1 = __float_as_uint(sm[VSO + (dv0 + gid + 8) * 72 + kk + tig]);
                unsigned a2 = __float_as_uint(sm[VSO + (dv0 + gid) * 72 + kk + tig + 4]);
                unsigned a3 = __float_as_uint(sm[VSO + (dv0 + gid + 8) * 72 + kk + tig + 4]);
                mma_tf32(oc[mt][0], a0, a1, a2, a3, p0[0], p1[0]);
                mma_tf32(oc[mt][1], a0, a1, a2, a3, p0[1], p1[1]);
            }
        }
    }

    // finalize: 1/sum, store O^T directly ([dv][q] orientation)
    if (tig == 0) { sm[SCO + qiA] = 1.f / sA; sm[SCO + qiB] = 1.f / sB; }
    __syncthreads();
    float si[2][2];
#pragma unroll
    for (int n2 = 0; n2 < 2; n2++)
#pragma unroll
        for (int j = 0; j < 2; j++)
            si[n2][j] = sm[SCO + qrow + n2 * 8 + 2 * tig + j];
    float* ob = attn_out + ((long long)b * 256 + h * 32) * 1024 + q0;
#pragma unroll
    for (int mt = 0; mt < 2; mt++)
#pragma unroll
        for (int n2 = 0; n2 < 2; n2++) {
            int dv0 = mt * 16 + gid;
            int qq = qrow + n2 * 8 + 2 * tig;
            *(float2*)&ob[(long long)dv0 * 1024 + qq] =
                make_float2(oc[mt][n2].x * si[n2][0], oc[mt][n2].y * si[n2][1]);
            *(float2*)&ob[(long long)(dv0 + 8) * 1024 + qq] =
                make_float2(oc[mt][n2].z * si[n2][0], oc[mt][n2].w * si[n2][1]);
        }
}

// ---------------- launch ----------------
extern "C" void kernel_launch(void* const* d_in, const int* in_sizes, int n_in,
                              void* d_out, int out_size) {
    const float* x      = (const float*)d_in[0];
    const float* w_qkv  = (const float*)d_in[1];
    const float* b_qkv  = (const float*)d_in[2];
    const float* w_attn = (const float*)d_in[3];
    const float* b_attn = (const float*)d_in[4];
    const float* w_out  = (const float*)d_in[5];
    const float* b_out  = (const float*)d_in[6];
    const float* relw   = (const float*)d_in[7];
    const float* relh   = (const float*)d_in[8];
    float* out = (float*)d_out;

    float *qkv, *col, *attn;
    cudaGetSymbolAddress((void**)&qkv,  g_qkv);
    cudaGetSymbolAddress((void**)&col,  g_col);
    cudaGetSymbolAddress((void**)&attn, g_attn);

    const int ATTN_SMEM = ATTN_SM_FLOATS * 4;
    cudaFuncSetAttribute(attn_mma, cudaFuncAttributeMaxDynamicSharedMemorySize, ATTN_SMEM);

    im2col_kernel<<<73728, 256>>>(x, col);

    // qkv 1x1: [768,256]x[256,1024], q rows scaled by dkh^-0.5
    sgemm_tf32<<<dim3(8, 6, 8), 256>>>(w_qkv, x, qkv, b_qkv,
                                       768, 1024, 256,
                                       256LL * 1024, 768LL * 1024, 0,
                                       0.17677669529663687f, 256);

    // conv GEMM: [256,2304]x[2304,1024] -> out rows 0..255
    sgemm_tf32<<<dim3(8, 2, 8), 256>>>(w_out, col, out, b_out,
                                       256, 1024, 2304,
                                       2304LL * 1024, 512LL * 1024, 0,
                                       1.f, 0);

    attn_mma<<<dim3(16, 64), 128, ATTN_SMEM>>>(qkv, relw, relh, attn);

    // final 1x1: [256,256]x[256,1024] -> out rows 256..511
    sgemm_tf32<<<dim3(8, 2, 8), 256>>>(w_attn, attn, out, b_attn,
                                       256, 1024, 256,
                                       256LL * 1024, 512LL * 1024, 256,
                                       1.f, 0);
}

// round 4
// speedup vs baseline: 5.5084x; 1.6482x over previous
#include <cuda_runtime.h>

// ---------------- scratch ----------------
__device__ float g_qkv [8LL * 768 * 1024];
__device__ float g_attn[8LL * 256 * 1024];

__device__ __forceinline__ unsigned cvt_tf32(float x) {
    unsigned r;
    asm("cvt.rna.tf32.f32 %0, %1;" : "=r"(r) : "f"(x));
    return r;
}
__device__ __forceinline__ void mma_tf32(float4& c, unsigned a0, unsigned a1,
                                         unsigned a2, unsigned a3,
                                         unsigned b0, unsigned b1) {
    asm volatile(
        "mma.sync.aligned.m16n8k8.row.col.f32.tf32.tf32.f32 "
        "{%0,%1,%2,%3}, {%4,%5,%6,%7}, {%8,%9}, {%0,%1,%2,%3};"
        : "+f"(c.x), "+f"(c.y), "+f"(c.z), "+f"(c.w)
        : "r"(a0), "r"(a1), "r"(a2), "r"(a3), "r"(b0), "r"(b1));
}

// ---------------- tf32 GEMM: 128x128 tile, BK=32, 8 warps ----------------
__global__ __launch_bounds__(256) void sgemm_tf32(
    const float* __restrict__ A, const float* __restrict__ X,
    float* __restrict__ C, const float* __restrict__ bias,
    int M, int N, int K, long long sX, long long sC, int crow,
    float qscale, int qrows)
{
    __shared__ float As[32 * 136];
    __shared__ float Bs[32 * 136];
    const int bz = blockIdx.z;
    const float* Xb = X + (long long)bz * sX;
    float* Cb = C + (long long)bz * sC;
    const int row0 = blockIdx.y * 128, col0 = blockIdx.x * 128;
    const int t = threadIdx.x;
    const int wid = t >> 5, lane = t & 31;
    const int gid = lane >> 2, tig = lane & 3;
    const int wm = wid >> 1, wn = wid & 1;
    const int ar = t >> 1, aks = (t & 1) * 16;
    const int br = t >> 3, bc = (t & 7) * 4;
    const float* Ap = A + (long long)(row0 + ar) * K + aks;
    const float* Xp = Xb + (long long)br * N + col0 + bc;

    float4 pa[4], pb[4];
#pragma unroll
    for (int j = 0; j < 4; j++) {
        pa[j] = *(const float4*)(Ap + 4 * j);
        pb[j] = *(const float4*)(Xp + 32 * j);
    }
    float4 acc[2][8];
#pragma unroll
    for (int mt = 0; mt < 2; mt++)
#pragma unroll
        for (int nt = 0; nt < 8; nt++) acc[mt][nt] = make_float4(0.f, 0.f, 0.f, 0.f);

    for (int k0 = 0;; ) {
#pragma unroll
        for (int j = 0; j < 4; j++) {
            As[(aks + 4 * j + 0) * 136 + ar] = __uint_as_float(cvt_tf32(pa[j].x));
            As[(aks + 4 * j + 1) * 136 + ar] = __uint_as_float(cvt_tf32(pa[j].y));
            As[(aks + 4 * j + 2) * 136 + ar] = __uint_as_float(cvt_tf32(pa[j].z));
            As[(aks + 4 * j + 3) * 136 + ar] = __uint_as_float(cvt_tf32(pa[j].w));
            float4 bb;
            bb.x = __uint_as_float(cvt_tf32(pb[j].x));
            bb.y = __uint_as_float(cvt_tf32(pb[j].y));
            bb.z = __uint_as_float(cvt_tf32(pb[j].z));
            bb.w = __uint_as_float(cvt_tf32(pb[j].w));
            *(float4*)&Bs[br * 136 + bc + 32 * j] = bb;
        }
        __syncthreads();
        bool last = (k0 + 32 >= K);
        if (!last) {
#pragma unroll
            for (int j = 0; j < 4; j++) {
                pa[j] = *(const float4*)(Ap + k0 + 32 + 4 * j);
                pb[j] = *(const float4*)(Xp + (long long)(k0 + 32) * N + 32 * j);
            }
        }
#pragma unroll
        for (int ks = 0; ks < 4; ks++) {
            const int kk = ks * 8;
            unsigned a[2][4];
#pragma unroll
            for (int mt = 0; mt < 2; mt++) {
                int m0 = wm * 32 + mt * 16;
                a[mt][0] = __float_as_uint(As[(kk + tig) * 136 + m0 + gid]);
                a[mt][1] = __float_as_uint(As[(kk + tig) * 136 + m0 + gid + 8]);
                a[mt][2] = __float_as_uint(As[(kk + tig + 4) * 136 + m0 + gid]);
                a[mt][3] = __float_as_uint(As[(kk + tig + 4) * 136 + m0 + gid + 8]);
            }
#pragma unroll
            for (int nt = 0; nt < 8; nt++) {
                int n0 = wn * 64 + nt * 8;
                unsigned b0 = __float_as_uint(Bs[(kk + tig) * 136 + n0 + gid]);
                unsigned b1 = __float_as_uint(Bs[(kk + tig + 4) * 136 + n0 + gid]);
                mma_tf32(acc[0][nt], a[0][0], a[0][1], a[0][2], a[0][3], b0, b1);
                mma_tf32(acc[1][nt], a[1][0], a[1][1], a[1][2], a[1][3], b0, b1);
            }
        }
        __syncthreads();
        k0 += 32;
        if (last) break;
    }
#pragma unroll
    for (int mt = 0; mt < 2; mt++) {
        int rA = row0 + wm * 32 + mt * 16 + gid;
        int rB = rA + 8;
        float bA = bias ? bias[rA] : 0.f, bB = bias ? bias[rB] : 0.f;
        float sA = (rA < qrows) ? qscale : 1.f, sB = (rB < qrows) ? qscale : 1.f;
#pragma unroll
        for (int nt = 0; nt < 8; nt++) {
            int cc = col0 + wn * 64 + nt * 8 + 2 * tig;
            *(float2*)&Cb[(long long)(crow + rA) * N + cc] =
                make_float2((acc[mt][nt].x + bA) * sA, (acc[mt][nt].y + bA) * sA);
            *(float2*)&Cb[(long long)(crow + rB) * N + cc] =
                make_float2((acc[mt][nt].z + bB) * sB, (acc[mt][nt].w + bB) * sB);
        }
    }
}

// ---------------- implicit-im2col conv GEMM (3x3 pad1 on 32x32) ----------------
// A = w_out [256][2304], virtual B[k][n] = x[b][k/9][n>>5 + (k%9)/3 -1][ (n&31) + (k%9)%3 -1 ]
__global__ __launch_bounds__(256) void conv_gemm_tf32(
    const float* __restrict__ A, const float* __restrict__ x,
    float* __restrict__ C, const float* __restrict__ bias,
    long long sC)
{
    const int N = 1024, K = 2304;
    __shared__ float As[32 * 136];
    __shared__ float Bs[32 * 136];
    const int bz = blockIdx.z;
    const float* Xb = x + (long long)bz * 256 * 1024;
    float* Cb = C + (long long)bz * sC;
    const int row0 = blockIdx.y * 128, col0 = blockIdx.x * 128;
    const int t = threadIdx.x;
    const int wid = t >> 5, lane = t & 31;
    const int gid = lane >> 2, tig = lane & 3;
    const int wm = wid >> 1, wn = wid & 1;
    const int ar = t >> 1, aks = (t & 1) * 16;
    const int br = t >> 3, bc = (t & 7) * 4;
    const float* Ap = A + (long long)(row0 + ar) * K + aks;

    float4 pa[4];
    float pbv[16];
#pragma unroll
    for (int j = 0; j < 4; j++) pa[j] = *(const float4*)(Ap + 4 * j);

    auto loadB = [&](int k0) {
        int k = k0 + br;
        int ci = k / 9, r = k - 9 * ci;
        int kh = r / 3, kw = r - 3 * kh;
        const float* xp = Xb + (long long)ci * 1024 + (kh - 1) * 32 + (kw - 1);
#pragma unroll
        for (int j = 0; j < 4; j++) {
#pragma unroll
            for (int i = 0; i < 4; i++) {
                int n = col0 + bc + 32 * j + i;
                int y = n >> 5, xx = n & 31;
                bool ok = (y + kh >= 1) && (y + kh <= 32) && (xx + kw >= 1) && (xx + kw <= 32);
                pbv[j * 4 + i] = ok ? xp[n] : 0.f;
            }
        }
    };
    loadB(0);

    float4 acc[2][8];
#pragma unroll
    for (int mt = 0; mt < 2; mt++)
#pragma unroll
        for (int nt = 0; nt < 8; nt++) acc[mt][nt] = make_float4(0.f, 0.f, 0.f, 0.f);

    for (int k0 = 0;; ) {
#pragma unroll
        for (int j = 0; j < 4; j++) {
            As[(aks + 4 * j + 0) * 136 + ar] = __uint_as_float(cvt_tf32(pa[j].x));
            As[(aks + 4 * j + 1) * 136 + ar] = __uint_as_float(cvt_tf32(pa[j].y));
            As[(aks + 4 * j + 2) * 136 + ar] = __uint_as_float(cvt_tf32(pa[j].z));
            As[(aks + 4 * j + 3) * 136 + ar] = __uint_as_float(cvt_tf32(pa[j].w));
            float4 bb;
            bb.x = __uint_as_float(cvt_tf32(pbv[j * 4 + 0]));
            bb.y = __uint_as_float(cvt_tf32(pbv[j * 4 + 1]));
            bb.z = __uint_as_float(cvt_tf32(pbv[j * 4 + 2]));
            bb.w = __uint_as_float(cvt_tf32(pbv[j * 4 + 3]));
            *(float4*)&Bs[br * 136 + bc + 32 * j] = bb;
        }
        __syncthreads();
        bool last = (k0 + 32 >= K);
        if (!last) {
#pragma unroll
            for (int j = 0; j < 4; j++) pa[j] = *(const float4*)(Ap + k0 + 32 + 4 * j);
            loadB(k0 + 32);
        }
#pragma unroll
        for (int ks = 0; ks < 4; ks++) {
            const int kk = ks * 8;
            unsigned a[2][4];
#pragma unroll
            for (int mt = 0; mt < 2; mt++) {
                int m0 = wm * 32 + mt * 16;
                a[mt][0] = __float_as_uint(As[(kk + tig) * 136 + m0 + gid]);
                a[mt][1] = __float_as_uint(As[(kk + tig) * 136 + m0 + gid + 8]);
                a[mt][2] = __float_as_uint(As[(kk + tig + 4) * 136 + m0 + gid]);
                a[mt][3] = __float_as_uint(As[(kk + tig + 4) * 136 + m0 + gid + 8]);
            }
#pragma unroll
            for (int nt = 0; nt < 8; nt++) {
                int n0 = wn * 64 + nt * 8;
                unsigned b0 = __float_as_uint(Bs[(kk + tig) * 136 + n0 + gid]);
                unsigned b1 = __float_as_uint(Bs[(kk + tig + 4) * 136 + n0 + gid]);
                mma_tf32(acc[0][nt], a[0][0], a[0][1], a[0][2], a[0][3], b0, b1);
                mma_tf32(acc[1][nt], a[1][0], a[1][1], a[1][2], a[1][3], b0, b1);
            }
        }
        __syncthreads();
        k0 += 32;
        if (last) break;
    }
#pragma unroll
    for (int mt = 0; mt < 2; mt++) {
        int rA = row0 + wm * 32 + mt * 16 + gid;
        int rB = rA + 8;
        float bA = bias[rA], bB = bias[rB];
#pragma unroll
        for (int nt = 0; nt < 8; nt++) {
            int cc = col0 + wn * 64 + nt * 8 + 2 * tig;
            *(float2*)&Cb[(long long)rA * N + cc] =
                make_float2(acc[mt][nt].x + bA, acc[mt][nt].y + bA);
            *(float2*)&Cb[(long long)rB * N + cc] =
                make_float2(acc[mt][nt].z + bB, acc[mt][nt].w + bB);
        }
    }
}

// ---------------- tensor-core flash attention, ping-pong buffers ----------------
// smem floats: BUF0 0..4608 (K 2304 | V 2304), BUF1 4608..9216,
// PSO 9216 (rel staging in prologue; P [64][72] in loop), EHO 13824 (64x64), SCO 17920
#define BUF0 0
#define BUF1 4608
#define PSO  9216
#define EHO  13824
#define SCO  17920
#define ATTN_SM_FLOATS 17984

__global__ __launch_bounds__(128) void attn_mma(
    const float* __restrict__ qkv,
    const float* __restrict__ relw,   // [63][32]
    const float* __restrict__ relh,   // [63][32]
    float* __restrict__ attn_out)     // [B][256][1024]
{
    extern __shared__ float sm[];
    const int bh = blockIdx.y;
    const int b = bh >> 3, h = bh & 7;
    const int bx = blockIdx.x;
    const int q0 = bx * 64;
    const int t = threadIdx.x;
    const int wid = t >> 5, lane = t & 31;
    const int gid = lane >> 2, tig = lane & 3;
    const int qrow = wid * 16;

    const float* qb = qkv + ((long long)b * 768 +       h * 32) * 1024;
    const float* kb = qkv + ((long long)b * 768 + 256 + h * 32) * 1024;
    const float* vb = qkv + ((long long)b * 768 + 512 + h * 32) * 1024;

    // prologue: Q as [q][d] (stride 36) into BUF0, rel tables (stride 36) into PSO
    for (int i = t; i < 2048; i += 128) {
        int d = i >> 6, qi = i & 63;
        sm[BUF0 + qi * 36 + d] = qb[d * 1024 + q0 + qi];
    }
    for (int i = t; i < 2016; i += 128) {
        int m = i >> 5, d = i & 31;
        sm[PSO + m * 36 + d]        = relw[i];
        sm[PSO + 2268 + m * 36 + d] = relh[i];
    }
    __syncthreads();

    // eh table [qi][m] (64x64, m<63 valid)
    for (int e = t; e < 4096; e += 128) {
        int qi = e >> 6, m = e & 63;
        float s = 0.f;
        if (m < 63) {
            const float* qp = sm + BUF0 + qi * 36;
            const float* rp = sm + PSO + 2268 + m * 36;
#pragma unroll
            for (int d = 0; d < 32; d += 4) {
                float4 q4 = *(const float4*)(qp + d);
                float4 r4 = *(const float4*)(rp + d);
                s += q4.x * r4.x + q4.y * r4.y + q4.z * r4.z + q4.w * r4.w;
            }
        }
        sm[EHO + e] = s;
    }

    // Q a-fragments + ew registers
    const int qiA = qrow + gid, qiB = qiA + 8;
    unsigned qa[4][4];
#pragma unroll
    for (int ks = 0; ks < 4; ks++) {
        int kd = ks * 8;
        qa[ks][0] = cvt_tf32(sm[BUF0 + qiA * 36 + kd + tig]);
        qa[ks][1] = cvt_tf32(sm[BUF0 + qiB * 36 + kd + tig]);
        qa[ks][2] = cvt_tf32(sm[BUF0 + qiA * 36 + kd + tig + 4]);
        qa[ks][3] = cvt_tf32(sm[BUF0 + qiB * 36 + kd + tig + 4]);
    }
    float ewreg[2][8];
#pragma unroll
    for (int rr = 0; rr < 2; rr++) {
        int qi = rr ? qiB : qiA;
        const float* qp = sm + BUF0 + qi * 36;
#pragma unroll
        for (int e = 0; e < 8; e++) {
            int yk = (e >> 1) * 8 + tig * 2 + (e & 1);
            int m = yk - (qi & 31) + 31;
            const float* rp = sm + PSO + m * 36;
            float s = 0.f;
#pragma unroll
            for (int d = 0; d < 32; d += 4) {
                float4 q4 = *(const float4*)(qp + d);
                float4 r4 = *(const float4*)(rp + d);
                s += q4.x * r4.x + q4.y * r4.y + q4.z * r4.z + q4.w * r4.w;
            }
            ewreg[rr][e] = s;
        }
    }
    __syncthreads();

    // stage tile 0 into BUF0 (overwrites Q staging; fragments are in regs)
    {
        float4 kreg[4], vreg[4];
#pragma unroll
        for (int j = 0; j < 4; j++) {
            int fi = j * 128 + t, d = fi >> 4, c = (fi & 15) * 4;
            kreg[j] = *(const float4*)(kb + d * 1024 + c);
            vreg[j] = *(const float4*)(vb + d * 1024 + c);
        }
#pragma unroll
        for (int j = 0; j < 4; j++) {
            int fi = j * 128 + t, d = fi >> 4, c = (fi & 15) * 4;
            *(float4*)&sm[BUF0 + d * 72 + c]        = kreg[j];
            *(float4*)&sm[BUF0 + 2304 + d * 72 + c] = vreg[j];
        }
    }
    __syncthreads();

    const int hqA = 2 * bx + (qiA >> 5);
    const int hqB = 2 * bx + (qiB >> 5);
    float mA = -1e30f, mB = -1e30f, sA = 0.f, sB = 0.f;
    float4 oc[2][2];
#pragma unroll
    for (int mt = 0; mt < 2; mt++)
#pragma unroll
        for (int n2 = 0; n2 < 2; n2++) oc[mt][n2] = make_float4(0.f, 0.f, 0.f, 0.f);

    float4 kreg[4], vreg[4];
    for (int tile = 0; tile < 16; tile++) {
        const int cur = BUF0 + (tile & 1) * 4608;
        const int nxt = BUF0 + ((tile + 1) & 1) * 4608;
        const bool more = (tile < 15);
        if (more) {
            int k0n = (tile + 1) * 64;
#pragma unroll
            for (int j = 0; j < 4; j++) {
                int fi = j * 128 + t, d = fi >> 4, c = (fi & 15) * 4;
                kreg[j] = *(const float4*)(kb + d * 1024 + k0n + c);
                vreg[j] = *(const float4*)(vb + d * 1024 + k0n + c);
            }
        }

        // S = Q K^T (raw fp32 operands; HW truncates to tf32)
        float4 sc4[8];
#pragma unroll
        for (int nt = 0; nt < 8; nt++) sc4[nt] = make_float4(0.f, 0.f, 0.f, 0.f);
#pragma unroll
        for (int ks = 0; ks < 4; ks++) {
            int kd = ks * 8;
#pragma unroll
            for (int nt = 0; nt < 8; nt++) {
                unsigned b0 = __float_as_uint(sm[cur + (kd + tig) * 72 + nt * 8 + gid]);
                unsigned b1 = __float_as_uint(sm[cur + (kd + tig + 4) * 72 + nt * 8 + gid]);
                mma_tf32(sc4[nt], qa[ks][0], qa[ks][1], qa[ks][2], qa[ks][3], b0, b1);
            }
        }

        // rel add + online softmax
        int xk = tile * 2;
        float ehA0 = sm[EHO + qiA * 64 + xk - hqA + 31];
        float ehA1 = sm[EHO + qiA * 64 + xk + 1 - hqA + 31];
        float ehB0 = sm[EHO + qiB * 64 + xk - hqB + 31];
        float ehB1 = sm[EHO + qiB * 64 + xk + 1 - hqB + 31];
        float mxA = -1e30f, mxB = -1e30f;
#pragma unroll
        for (int nt = 0; nt < 8; nt++) {
            float ha = (nt < 4) ? ehA0 : ehA1;
            float hb = (nt < 4) ? ehB0 : ehB1;
            sc4[nt].x += ewreg[0][(nt & 3) * 2 + 0] + ha;
            sc4[nt].y += ewreg[0][(nt & 3) * 2 + 1] + ha;
            sc4[nt].z += ewreg[1][(nt & 3) * 2 + 0] + hb;
            sc4[nt].w += ewreg[1][(nt & 3) * 2 + 1] + hb;
            mxA = fmaxf(mxA, fmaxf(sc4[nt].x, sc4[nt].y));
            mxB = fmaxf(mxB, fmaxf(sc4[nt].z, sc4[nt].w));
        }
        mxA = fmaxf(mxA, __shfl_xor_sync(0xffffffffu, mxA, 1));
        mxA = fmaxf(mxA, __shfl_xor_sync(0xffffffffu, mxA, 2));
        mxB = fmaxf(mxB, __shfl_xor_sync(0xffffffffu, mxB, 1));
        mxB = fmaxf(mxB, __shfl_xor_sync(0xffffffffu, mxB, 2));
        float nmA = fmaxf(mA, mxA), nmB = fmaxf(mB, mxB);
        float scA = __expf(mA - nmA), scB = __expf(mB - nmB);
        float rsA = 0.f, rsB = 0.f;
#pragma unroll
        for (int nt = 0; nt < 8; nt++) {
            float px = __expf(sc4[nt].x - nmA), py = __expf(sc4[nt].y - nmA);
            float pz = __expf(sc4[nt].z - nmB), pw = __expf(sc4[nt].w - nmB);
            rsA += px + py; rsB += pz + pw;
            int cc = nt * 8 + 2 * tig;
            *(float2*)&sm[PSO + qiA * 72 + cc] = make_float2(px, py);
            *(float2*)&sm[PSO + qiB * 72 + cc] = make_float2(pz, pw);
        }
        rsA += __shfl_xor_sync(0xffffffffu, rsA, 1);
        rsA += __shfl_xor_sync(0xffffffffu, rsA, 2);
        rsB += __shfl_xor_sync(0xffffffffu, rsB, 1);
        rsB += __shfl_xor_sync(0xffffffffu, rsB, 2);
        sA = sA * scA + rsA; mA = nmA;
        sB = sB * scB + rsB; mB = nmB;
        if (tig == 0) { sm[SCO + qiA] = scA; sm[SCO + qiB] = scB; }
        __syncwarp();

        // O^T = V P^T (rescale first)
        float scq[2][2];
#pragma unroll
        for (int n2 = 0; n2 < 2; n2++)
#pragma unroll
            for (int j = 0; j < 2; j++)
                scq[n2][j] = sm[SCO + qrow + n2 * 8 + 2 * tig + j];
#pragma unroll
        for (int mt = 0; mt < 2; mt++)
#pragma unroll
            for (int n2 = 0; n2 < 2; n2++) {
                oc[mt][n2].x *= scq[n2][0]; oc[mt][n2].y *= scq[n2][1];
                oc[mt][n2].z *= scq[n2][0]; oc[mt][n2].w *= scq[n2][1];
            }
#pragma unroll
        for (int ks = 0; ks < 8; ks++) {
            int kk = ks * 8;
            unsigned p0[2], p1[2];
#pragma unroll
            for (int n2 = 0; n2 < 2; n2++) {
                p0[n2] = __float_as_uint(sm[PSO + (qrow + n2 * 8 + gid) * 72 + kk + tig]);
                p1[n2] = __float_as_uint(sm[PSO + (qrow + n2 * 8 + gid) * 72 + kk + tig + 4]);
            }
#pragma unroll
            for (int mt = 0; mt < 2; mt++) {
                int dv0 = mt * 16;
                unsigned a0 = __float_as_uint(sm[cur + 2304 + (dv0 + gid) * 72 + kk + tig]);
                unsigned a1 = __float_as_uint(sm[cur + 2304 + (dv0 + gid + 8) * 72 + kk + tig]);
                unsigned a2 = __float_as_uint(sm[cur + 2304 + (dv0 + gid) * 72 + kk + tig + 4]);
                unsigned a3 = __float_as_uint(sm[cur + 2304 + (dv0 + gid + 8) * 72 + kk + tig + 4]);
                mma_tf32(oc[mt][0], a0, a1, a2, a3, p0[0], p1[0]);
                mma_tf32(oc[mt][1], a0, a1, a2, a3, p0[1], p1[1]);
            }
        }

        if (more) {
#pragma unroll
            for (int j = 0; j < 4; j++) {
                int fi = j * 128 + t, d = fi >> 4, c = (fi & 15) * 4;
                *(float4*)&sm[nxt + d * 72 + c]        = kreg[j];
                *(float4*)&sm[nxt + 2304 + d * 72 + c] = vreg[j];
            }
        }
        __syncthreads();
    }

    if (tig == 0) { sm[SCO + qiA] = 1.f / sA; sm[SCO + qiB] = 1.f / sB; }
    __syncwarp();
    float si[2][2];
#pragma unroll
    for (int n2 = 0; n2 < 2; n2++)
#pragma unroll
        for (int j = 0; j < 2; j++)
            si[n2][j] = sm[SCO + qrow + n2 * 8 + 2 * tig + j];
    float* ob = attn_out + ((long long)b * 256 + h * 32) * 1024 + q0;
#pragma unroll
    for (int mt = 0; mt < 2; mt++)
#pragma unroll
        for (int n2 = 0; n2 < 2; n2++) {
            int dv0 = mt * 16 + gid;
            int qq = qrow + n2 * 8 + 2 * tig;
            *(float2*)&ob[(long long)dv0 * 1024 + qq] =
                make_float2(oc[mt][n2].x * si[n2][0], oc[mt][n2].y * si[n2][1]);
            *(float2*)&ob[(long long)(dv0 + 8) * 1024 + qq] =
                make_float2(oc[mt][n2].z * si[n2][0], oc[mt][n2].w * si[n2][1]);
        }
}

// ---------------- launch ----------------
extern "C" void kernel_launch(void* const* d_in, const int* in_sizes, int n_in,
                              void* d_out, int out_size) {
    const float* x      = (const float*)d_in[0];
    const float* w_qkv  = (const float*)d_in[1];
    const float* b_qkv  = (const float*)d_in[2];
    const float* w_attn = (const float*)d_in[3];
    const float* b_attn = (const float*)d_in[4];
    const float* w_out  = (const float*)d_in[5];
    const float* b_out  = (const float*)d_in[6];
    const float* relw   = (const float*)d_in[7];
    const float* relh   = (const float*)d_in[8];
    float* out = (float*)d_out;

    float *qkv, *attn;
    cudaGetSymbolAddress((void**)&qkv,  g_qkv);
    cudaGetSymbolAddress((void**)&attn, g_attn);

    const int ATTN_SMEM = ATTN_SM_FLOATS * 4;
    cudaFuncSetAttribute(attn_mma, cudaFuncAttributeMaxDynamicSharedMemorySize, ATTN_SMEM);

    // qkv 1x1 GEMM (q rows scaled)
    sgemm_tf32<<<dim3(8, 6, 8), 256>>>(w_qkv, x, qkv, b_qkv,
                                       768, 1024, 256,
                                       256LL * 1024, 768LL * 1024, 0,
                                       0.17677669529663687f, 256);

    // implicit conv GEMM -> out rows 0..255
    conv_gemm_tf32<<<dim3(8, 2, 8), 256>>>(w_out, x, out, b_out, 512LL * 1024);

    attn_mma<<<dim3(16, 64), 128, ATTN_SMEM>>>(qkv, relw, relh, attn);

    // final 1x1 -> out rows 256..511
    sgemm_tf32<<<dim3(8, 2, 8), 256>>>(w_attn, attn, out, b_attn,
                                       256, 1024, 256,
                                       256LL * 1024, 512LL * 1024, 256,
                                       1.f, 0);
}